// round 6
// baseline (speedup 1.0000x reference)
#include <cuda_runtime.h>

#define HH 2048
#define WW 2048
#define NB 1024

#define RG  256          // region size (pixels), 8x8 regions
#define NRX (WW / RG)    // 8
#define NRY (HH / RG)    // 8
#define NR  (NRX * NRY)  // 64

#define TW 128           // tile width
#define TH 16            // tile height
#define BT 512           // paint threads per block (32 x 16)

// Per-region compacted lists (descending paint order: entry 0 = last-painted).
__device__ ushort4 g_rb[NR][NB];   // pixel bounds {y1,x1,y2,x2}
__device__ float4  g_rv[NR][NB];   // original normalized coords
__device__ int     g_rlen[NR];

// ---------------------------------------------------------------------------
// Level 1: one block (1024 threads) per 256x256 region. Thread t handles box
// (NB-1-t) so thread order == scan order (descending paint index). Truncate
// at the first region-covering box; stable single-ballot-chunk compaction.
// ---------------------------------------------------------------------------
__global__ void __launch_bounds__(NB) region_cull(const float* __restrict__ boxes) {
    __shared__ int wcnt[32], woff[32];
    __shared__ int s_minc;

    const int rid = blockIdx.x;
    const int rx0 = (rid & (NRX - 1)) * RG;
    const int ry0 = (rid / NRX) * RG;
    const int rx1 = rx0 + RG;
    const int ry1 = ry0 + RG;

    const int tid  = threadIdx.x;
    const int wid  = tid >> 5;
    const int lane = tid & 31;

    if (tid == 0) s_minc = NB;   // "no covering box"
    __syncthreads();

    const int i = (NB - 1) - tid;
    float4 v = *(const float4*)(boxes + 4 * i);
    // match reference: truncate toward zero, then clamp
    int y1 = max(0,  (int)(v.x * (float)HH));
    int x1 = max(0,  (int)(v.y * (float)WW));
    int y2 = min(HH, (int)(v.z * (float)HH));
    int x2 = min(WW, (int)(v.w * (float)WW));

    bool inter = (y1 < y2) && (x1 < x2) &&
                 (y1 < ry1) && (y2 > ry0) && (x1 < rx1) && (x2 > rx0);
    bool cover = inter && (y1 <= ry0) && (y2 >= ry1) && (x1 <= rx0) && (x2 >= rx1);

    if (cover) atomicMin(&s_minc, tid);
    __syncthreads();

    // Boxes scanned after (threads >) the first covering box are unreachable.
    inter = inter && (tid <= s_minc);

    unsigned m = __ballot_sync(0xffffffffu, inter);
    if (lane == 0) wcnt[wid] = __popc(m);
    __syncthreads();
    if (tid == 0) {
        int s = 0;
        #pragma unroll
        for (int w = 0; w < 32; ++w) { woff[w] = s; s += wcnt[w]; }
        g_rlen[rid] = s;
    }
    __syncthreads();
    if (inter) {
        int pos = woff[wid] + __popc(m & ((1u << lane) - 1u));
        g_rb[rid][pos] = make_ushort4((unsigned short)y1, (unsigned short)x1,
                                      (unsigned short)y2, (unsigned short)x2);
        g_rv[rid][pos] = v;
    }
}

// ---------------------------------------------------------------------------
// Level 2: one block per 128x16 tile. Cull the (short) region list down to
// tile-intersecting boxes in shared, early-stopping at a tile-covering box,
// then per-pixel first-hit scan + 5 coalesced float4 stores.
// ---------------------------------------------------------------------------
__global__ void __launch_bounds__(BT) paint_kernel(float* __restrict__ out) {
    __shared__ ushort4 sb[NB];        // 8 KB
    __shared__ float4  sv[NB];        // 16 KB
    __shared__ int s_len, s_stop;
    __shared__ int wcnt[BT / 32], woff[BT / 32];

    const int tid  = threadIdx.y * 32 + threadIdx.x;
    const int wid  = tid >> 5;
    const int lane = tid & 31;

    const int tx0 = blockIdx.x * TW;
    const int ty0 = blockIdx.y * TH;
    const int tx1 = tx0 + TW;
    const int ty1 = ty0 + TH;

    const int rid = (ty0 / RG) * NRX + (tx0 / RG);
    const int L   = g_rlen[rid];
    const ushort4* __restrict__ rb = g_rb[rid];
    const float4*  __restrict__ rv = g_rv[rid];

    if (tid == 0) { s_len = 0; s_stop = 0; }
    __syncthreads();

    // Usually a single chunk (L <= 512).
    for (int base = 0; base < L; base += BT) {
        int j = base + tid;               // ascending j == scan order
        bool inter = false, full = false;
        ushort4 b;
        if (j < L) {
            b = rb[j];
            inter = (b.x < ty1) && (b.z > ty0) && (b.y < tx1) && (b.w > tx0);
            full  = inter && (b.x <= ty0) && (b.z >= ty1) &&
                             (b.y <= tx0) && (b.w >= tx1);
        }
        unsigned m = __ballot_sync(0xffffffffu, inter);
        if (lane == 0) wcnt[wid] = __popc(m);
        __syncthreads();
        if (tid == 0) {
            int s = s_len;
            #pragma unroll
            for (int w = 0; w < BT / 32; ++w) { woff[w] = s; s += wcnt[w]; }
            s_len = s;
        }
        __syncthreads();
        if (inter) {
            int pos = woff[wid] + __popc(m & ((1u << lane) - 1u));
            sb[pos] = b;
            sv[pos] = rv[j];
            if (full) s_stop = 1;         // benign race
        }
        __syncthreads();
        if (s_stop) break;
    }

    const int len = s_len;

    const int x0 = tx0 + threadIdx.x * 4;
    const int y  = ty0 + threadIdx.y;     // warp-uniform

    int i0 = -1, i1 = -1, i2 = -1, i3 = -1;
    if (len > 0) {
        ushort4 b = sb[0];
        for (int j = 0; j < len; ++j) {
            ushort4 bn = sb[(j + 1 < len) ? j + 1 : j];   // prefetch next
            if (y >= b.x && y < b.z) {                    // warp-uniform test
                if (i0 < 0 && (x0    ) >= b.y && (x0    ) < b.w) i0 = j;
                if (i1 < 0 && (x0 + 1) >= b.y && (x0 + 1) < b.w) i1 = j;
                if (i2 < 0 && (x0 + 2) >= b.y && (x0 + 2) < b.w) i2 = j;
                if (i3 < 0 && (x0 + 3) >= b.y && (x0 + 3) < b.w) i3 = j;
            }
            if ((i0 | i1 | i2 | i3) >= 0) break;          // all four found
            b = bn;
        }
    }

    float4 v0 = (i0 >= 0) ? sv[i0] : make_float4(0.f, 0.f, 0.f, 0.f);
    float4 v1 = (i1 >= 0) ? sv[i1] : make_float4(0.f, 0.f, 0.f, 0.f);
    float4 v2 = (i2 >= 0) ? sv[i2] : make_float4(0.f, 0.f, 0.f, 0.f);
    float4 v3 = (i3 >= 0) ? sv[i3] : make_float4(0.f, 0.f, 0.f, 0.f);

    float4 c0 = make_float4(i0 >= 0 ? 1.f : 0.f,
                            i1 >= 0 ? 1.f : 0.f,
                            i2 >= 0 ? 1.f : 0.f,
                            i3 >= 0 ? 1.f : 0.f);
    float4 c1 = make_float4(v0.x, v1.x, v2.x, v3.x);
    float4 c2 = make_float4(v0.y, v1.y, v2.y, v3.y);
    float4 c3 = make_float4(v0.z, v1.z, v2.z, v3.z);
    float4 c4 = make_float4(v0.w, v1.w, v2.w, v3.w);

    const size_t HWsz = (size_t)HH * (size_t)WW;
    size_t base = (size_t)y * WW + (size_t)x0;
    *(float4*)(out + 0 * HWsz + base) = c0;
    *(float4*)(out + 1 * HWsz + base) = c1;
    *(float4*)(out + 2 * HWsz + base) = c2;
    *(float4*)(out + 3 * HWsz + base) = c3;
    *(float4*)(out + 4 * HWsz + base) = c4;
}

extern "C" void kernel_launch(void* const* d_in, const int* in_sizes, int n_in,
                              void* d_out, int out_size) {
    const float* boxes = (const float*)d_in[0];
    float* out = (float*)d_out;

    region_cull<<<NR, NB>>>(boxes);

    dim3 block(32, 16);                       // 512 threads
    dim3 grid(WW / TW, HH / TH);              // (16, 128) = 2048 blocks
    paint_kernel<<<grid, block>>>(out);
}

// round 8
// speedup vs baseline: 1.1910x; 1.1910x over previous
#include <cuda_runtime.h>

#define HH 2048
#define WW 2048
#define NB 1024

#define TW 128           // tile width (pixels)
#define TH 16            // tile height (pixels)
#define BT 512           // threads per block (32 x 16)
#define NW (BT / 32)     // 16 warps

// ---------------------------------------------------------------------------
// Single fused kernel: one block per 128x16 tile.
// Phase 1: descending-order stable compaction of valid+tile-intersecting boxes
//          into shared (bounds computed inline), early stop at a box that
//          fully covers the tile.
// Phase 2: per-pixel first-hit scan with warp-uniform exit, then 5 coalesced
//          float4 stores.
// ---------------------------------------------------------------------------
__global__ void __launch_bounds__(BT) paint_kernel(const float* __restrict__ boxes,
                                                   float* __restrict__ out) {
    __shared__ ushort4 sb[NB];        // 8 KB  {y1,x1,y2,x2}
    __shared__ float4  sv[NB];        // 16 KB normalized coords
    __shared__ int s_len, s_stop;
    __shared__ int wcnt[NW], woff[NW];

    const int tid  = threadIdx.y * 32 + threadIdx.x;
    const int wid  = tid >> 5;
    const int lane = tid & 31;

    const int tx0 = blockIdx.x * TW;
    const int ty0 = blockIdx.y * TH;
    const int tx1 = tx0 + TW;
    const int ty1 = ty0 + TH;

    // ---------------- Phase 1: compaction ----------------
    #pragma unroll
    for (int chunk = 0; chunk < NB / BT; ++chunk) {
        const int i = (NB - 1) - chunk * BT - tid;   // tid 0 = highest index
        float4 v = *(const float4*)(boxes + 4 * i);
        // match reference: truncate toward zero, then clamp
        int y1 = max(0,  (int)(v.x * (float)HH));
        int x1 = max(0,  (int)(v.y * (float)WW));
        int y2 = min(HH, (int)(v.z * (float)HH));
        int x2 = min(WW, (int)(v.w * (float)WW));
        bool inter = (y1 < ty1) && (y2 > ty0) && (x1 < tx1) && (x2 > tx0) &&
                     (y1 < y2) && (x1 < x2);

        unsigned m = __ballot_sync(0xffffffffu, inter);
        if (chunk == 0 && tid == 0) s_stop = 0;
        if (lane == 0) wcnt[wid] = __popc(m);
        __syncthreads();

        if (wid == 0) {                               // shfl inclusive scan
            int c = (lane < NW) ? wcnt[lane] : 0;
            int inc = c;
            #pragma unroll
            for (int d = 1; d < NW; d <<= 1) {
                int t = __shfl_up_sync(0xffffffffu, inc, d);
                if (lane >= d) inc += t;
            }
            int base = chunk ? s_len : 0;
            if (lane < NW) woff[lane] = base + inc - c;
            if (lane == NW - 1) s_len = base + inc;
        }
        __syncthreads();

        if (inter) {
            int pos = woff[wid] + __popc(m & ((1u << lane) - 1u));
            sb[pos] = make_ushort4((unsigned short)y1, (unsigned short)x1,
                                   (unsigned short)y2, (unsigned short)x2);
            sv[pos] = v;
            if ((y1 <= ty0) & (y2 >= ty1) & (x1 <= tx0) & (x2 >= tx1))
                s_stop = 1;                           // benign race
        }
        __syncthreads();
        if (s_stop) break;                            // block-uniform
    }

    const int len = s_len;

    // ---------------- Phase 2: per-pixel first-hit scan ----------------
    const int x0 = tx0 + threadIdx.x * 4;
    const int y  = ty0 + threadIdx.y;                 // warp-uniform

    int j0 = -1, j1 = -1, j2 = -1, j3 = -1;
    int j = 0;
    for (; j + 1 < len; j += 2) {
        {
            ushort4 b = sb[j];
            if ((unsigned)(y - (int)b.x) < (unsigned)((int)b.z - (int)b.x)) {
                int rel = x0 - (int)b.y;
                unsigned w = (unsigned)((int)b.w - (int)b.y);
                if (j0 < 0 && (unsigned)(rel    ) < w) j0 = j;
                if (j1 < 0 && (unsigned)(rel + 1) < w) j1 = j;
                if (j2 < 0 && (unsigned)(rel + 2) < w) j2 = j;
                if (j3 < 0 && (unsigned)(rel + 3) < w) j3 = j;
            }
        }
        {
            ushort4 b = sb[j + 1];
            if ((unsigned)(y - (int)b.x) < (unsigned)((int)b.z - (int)b.x)) {
                int rel = x0 - (int)b.y;
                unsigned w = (unsigned)((int)b.w - (int)b.y);
                if (j0 < 0 && (unsigned)(rel    ) < w) j0 = j + 1;
                if (j1 < 0 && (unsigned)(rel + 1) < w) j1 = j + 1;
                if (j2 < 0 && (unsigned)(rel + 2) < w) j2 = j + 1;
                if (j3 < 0 && (unsigned)(rel + 3) < w) j3 = j + 1;
            }
        }
        if (__all_sync(0xffffffffu, (j0 | j1 | j2 | j3) >= 0)) break;  // uniform
    }
    if (j + 1 == len) {                               // odd tail
        ushort4 b = sb[j];
        if ((unsigned)(y - (int)b.x) < (unsigned)((int)b.z - (int)b.x)) {
            int rel = x0 - (int)b.y;
            unsigned w = (unsigned)((int)b.w - (int)b.y);
            if (j0 < 0 && (unsigned)(rel    ) < w) j0 = j;
            if (j1 < 0 && (unsigned)(rel + 1) < w) j1 = j;
            if (j2 < 0 && (unsigned)(rel + 2) < w) j2 = j;
            if (j3 < 0 && (unsigned)(rel + 3) < w) j3 = j;
        }
    }

    float4 v0 = (j0 >= 0) ? sv[j0] : make_float4(0.f, 0.f, 0.f, 0.f);
    float4 v1 = (j1 >= 0) ? sv[j1] : make_float4(0.f, 0.f, 0.f, 0.f);
    float4 v2 = (j2 >= 0) ? sv[j2] : make_float4(0.f, 0.f, 0.f, 0.f);
    float4 v3 = (j3 >= 0) ? sv[j3] : make_float4(0.f, 0.f, 0.f, 0.f);

    float4 c0 = make_float4(j0 >= 0 ? 1.f : 0.f,
                            j1 >= 0 ? 1.f : 0.f,
                            j2 >= 0 ? 1.f : 0.f,
                            j3 >= 0 ? 1.f : 0.f);
    float4 c1 = make_float4(v0.x, v1.x, v2.x, v3.x);
    float4 c2 = make_float4(v0.y, v1.y, v2.y, v3.y);
    float4 c3 = make_float4(v0.z, v1.z, v2.z, v3.z);
    float4 c4 = make_float4(v0.w, v1.w, v2.w, v3.w);

    const size_t HWsz = (size_t)HH * (size_t)WW;
    size_t base = (size_t)y * WW + (size_t)x0;
    *(float4*)(out + 0 * HWsz + base) = c0;
    *(float4*)(out + 1 * HWsz + base) = c1;
    *(float4*)(out + 2 * HWsz + base) = c2;
    *(float4*)(out + 3 * HWsz + base) = c3;
    *(float4*)(out + 4 * HWsz + base) = c4;
}

extern "C" void kernel_launch(void* const* d_in, const int* in_sizes, int n_in,
                              void* d_out, int out_size) {
    const float* boxes = (const float*)d_in[0];
    float* out = (float*)d_out;

    dim3 block(32, 16);                       // 512 threads
    dim3 grid(WW / TW, HH / TH);              // (16, 128) = 2048 blocks
    paint_kernel<<<grid, block>>>(boxes, out);
}

// round 9
// speedup vs baseline: 1.2092x; 1.0153x over previous
#include <cuda_runtime.h>

#define HH 2048
#define WW 2048
#define NB 1024

#define TW 128           // tile width (pixels)  == warp x-span
#define TH 16            // tile height (pixels) == warps per block
#define BT 512           // threads per block (32 x 16)
#define NW (BT / 32)     // 16 warps

// ---------------------------------------------------------------------------
// One block per 128x16 tile.
// Phase 1: descending-order stable compaction of valid+tile-intersecting boxes
//          into shared, early stop at a box fully covering the tile.
// Phase 2: warp = one tile row (y uniform). Lanes cooperatively y-test 32
//          boxes/iteration; only y-hitting boxes (ballot mask walk, ascending
//          = paint order) run the per-pixel capture body. Early exit when all
//          128 row pixels have found their box.
// ---------------------------------------------------------------------------
__global__ void __launch_bounds__(BT) paint_kernel(const float* __restrict__ boxes,
                                                   float* __restrict__ out) {
    __shared__ ushort4 sb[NB];        // 8 KB  {y1,x1,y2,x2}
    __shared__ float4  sv[NB];        // 16 KB normalized coords
    __shared__ int s_len, s_stop;
    __shared__ int wcnt[NW], woff[NW];

    const int tid  = threadIdx.y * 32 + threadIdx.x;
    const int wid  = tid >> 5;
    const int lane = tid & 31;

    const int tx0 = blockIdx.x * TW;
    const int ty0 = blockIdx.y * TH;
    const int tx1 = tx0 + TW;
    const int ty1 = ty0 + TH;

    // ---------------- Phase 1: compaction ----------------
    #pragma unroll
    for (int chunk = 0; chunk < NB / BT; ++chunk) {
        const int i = (NB - 1) - chunk * BT - tid;   // tid 0 = highest index
        float4 v = *(const float4*)(boxes + 4 * i);
        // match reference: truncate toward zero, then clamp
        int y1 = max(0,  (int)(v.x * (float)HH));
        int x1 = max(0,  (int)(v.y * (float)WW));
        int y2 = min(HH, (int)(v.z * (float)HH));
        int x2 = min(WW, (int)(v.w * (float)WW));
        bool inter = (y1 < ty1) && (y2 > ty0) && (x1 < tx1) && (x2 > tx0) &&
                     (y1 < y2) && (x1 < x2);

        unsigned m = __ballot_sync(0xffffffffu, inter);
        if (chunk == 0 && tid == 0) s_stop = 0;
        if (lane == 0) wcnt[wid] = __popc(m);
        __syncthreads();

        if (wid == 0) {                               // shfl inclusive scan
            int c = (lane < NW) ? wcnt[lane] : 0;
            int inc = c;
            #pragma unroll
            for (int d = 1; d < NW; d <<= 1) {
                int t = __shfl_up_sync(0xffffffffu, inc, d);
                if (lane >= d) inc += t;
            }
            int base = chunk ? s_len : 0;
            if (lane < NW) woff[lane] = base + inc - c;
            if (lane == NW - 1) s_len = base + inc;
        }
        __syncthreads();

        if (inter) {
            int pos = woff[wid] + __popc(m & ((1u << lane) - 1u));
            sb[pos] = make_ushort4((unsigned short)y1, (unsigned short)x1,
                                   (unsigned short)y2, (unsigned short)x2);
            sv[pos] = v;
            if ((y1 <= ty0) & (y2 >= ty1) & (x1 <= tx0) & (x2 >= tx1))
                s_stop = 1;                           // benign race
        }
        __syncthreads();
        if (s_stop) break;                            // block-uniform
    }

    const int len = s_len;

    // ---------------- Phase 2: cooperative y-filtered scan ----------------
    const int x0 = tx0 + threadIdx.x * 4;
    const int y  = ty0 + threadIdx.y;                 // warp-uniform

    int j0 = -1, j1 = -1, j2 = -1, j3 = -1;
    bool alldone = false;

    for (int base = 0; base < len && !alldone; base += 32) {
        // Each lane y-tests a different box (x-overlap is implied by tile
        // compaction, since the warp spans the full tile width).
        int j = base + lane;
        bool rowhit = false;
        if (j < len) {
            ushort4 b = sb[j];
            rowhit = (unsigned)(y - (int)b.x) < (unsigned)((int)b.z - (int)b.x);
        }
        unsigned m = __ballot_sync(0xffffffffu, rowhit);  // warp-uniform mask

        while (m) {                                   // ascending = paint order
            int k = __ffs(m) - 1;
            m &= m - 1;
            int jj = base + k;
            ushort4 b = sb[jj];                       // broadcast LDS
            int rel = x0 - (int)b.y;
            unsigned w = (unsigned)((int)b.w - (int)b.y);
            if (j0 < 0 && (unsigned)(rel    ) < w) j0 = jj;
            if (j1 < 0 && (unsigned)(rel + 1) < w) j1 = jj;
            if (j2 < 0 && (unsigned)(rel + 2) < w) j2 = jj;
            if (j3 < 0 && (unsigned)(rel + 3) < w) j3 = jj;
            if (__all_sync(0xffffffffu, (j0 | j1 | j2 | j3) >= 0)) {
                alldone = true;                       // warp-uniform
                break;
            }
        }
    }

    float4 v0 = (j0 >= 0) ? sv[j0] : make_float4(0.f, 0.f, 0.f, 0.f);
    float4 v1 = (j1 >= 0) ? sv[j1] : make_float4(0.f, 0.f, 0.f, 0.f);
    float4 v2 = (j2 >= 0) ? sv[j2] : make_float4(0.f, 0.f, 0.f, 0.f);
    float4 v3 = (j3 >= 0) ? sv[j3] : make_float4(0.f, 0.f, 0.f, 0.f);

    float4 c0 = make_float4(j0 >= 0 ? 1.f : 0.f,
                            j1 >= 0 ? 1.f : 0.f,
                            j2 >= 0 ? 1.f : 0.f,
                            j3 >= 0 ? 1.f : 0.f);
    float4 c1 = make_float4(v0.x, v1.x, v2.x, v3.x);
    float4 c2 = make_float4(v0.y, v1.y, v2.y, v3.y);
    float4 c3 = make_float4(v0.z, v1.z, v2.z, v3.z);
    float4 c4 = make_float4(v0.w, v1.w, v2.w, v3.w);

    const size_t HWsz = (size_t)HH * (size_t)WW;
    size_t base = (size_t)y * WW + (size_t)x0;
    *(float4*)(out + 0 * HWsz + base) = c0;
    *(float4*)(out + 1 * HWsz + base) = c1;
    *(float4*)(out + 2 * HWsz + base) = c2;
    *(float4*)(out + 3 * HWsz + base) = c3;
    *(float4*)(out + 4 * HWsz + base) = c4;
}

extern "C" void kernel_launch(void* const* d_in, const int* in_sizes, int n_in,
                              void* d_out, int out_size) {
    const float* boxes = (const float*)d_in[0];
    float* out = (float*)d_out;

    dim3 block(32, 16);                       // 512 threads
    dim3 grid(WW / TW, HH / TH);              // (16, 128) = 2048 blocks
    paint_kernel<<<grid, block>>>(boxes, out);
}